// round 13
// baseline (speedup 1.0000x reference)
#include <cuda_runtime.h>
#include <math.h>

typedef unsigned long long ull;
typedef unsigned int uint;

#define TT 8192
#define HH 512

// ---------------- scratch: packed {flag(hi32), h_bits(lo32)} mailboxes ----------------
__device__ __align__(256) ull g_p1[(TT + 1) * HH];
__device__ __align__(256) ull g_p2[(TT + 1) * HH];

// ---------------- primitives ----------------
__device__ __forceinline__ ulonglong2 ld_rlx2(const ull* p) {
    ulonglong2 v;
    asm volatile("ld.relaxed.gpu.global.v2.u64 {%0,%1}, [%2];"
                 : "=l"(v.x), "=l"(v.y) : "l"(p) : "memory");
    return v;
}
__device__ __forceinline__ void st_rlx(ull* p, ull v) {
    asm volatile("st.relaxed.gpu.global.u64 [%0], %1;" :: "l"(p), "l"(v) : "memory");
}
__device__ __forceinline__ ull packhf(unsigned flag, float h) {
    return ((ull)flag << 32) | (ull)__float_as_uint(h);
}
__device__ __forceinline__ float lo_f(ull v) { return __uint_as_float((unsigned)v); }
__device__ __forceinline__ unsigned hi_u(ull v) { return (unsigned)(v >> 32); }

__device__ __forceinline__ void ffma2(ull& acc, ull w, ull v) {
    asm("fma.rn.f32x2 %0, %1, %2, %0;" : "+l"(acc) : "l"(w), "l"(v));
}
__device__ __forceinline__ ull packf2(float a, float b) {
    ull r;
    asm("mov.b64 %0, {%1,%2};" : "=l"(r) : "f"(a), "f"(b));
    return r;
}
__device__ __forceinline__ float2 unpack2(ull v) {
    float a, b;
    asm("mov.b64 {%0,%1}, %2;" : "=f"(a), "=f"(b) : "l"(v));
    return make_float2(a, b);
}
__device__ __forceinline__ float tanh_fast(float x) {
    float r;
    asm("tanh.approx.f32 %0, %1;" : "=f"(r) : "f"(x));
    return r;
}
__device__ __forceinline__ float sig_fast(float x) {
    return fmaf(tanh_fast(0.5f * x), 0.5f, 0.5f);
}
__device__ __forceinline__ float logsigf_(float z) {
    if (z >= 0.0f) return -log1pf(expf(-z));
    return z - log1pf(expf(z));
}

// 2-deep pipelined poll of one v2 mailbox pair: two same-address loads in
// flight, alternating — samples the line ~2x per L2 round trip.
__device__ __forceinline__ ulonglong2 pollv2_pipe(const ull* p, unsigned tgt) {
    ulonglong2 v0 = ld_rlx2(p);
    ulonglong2 v1 = ld_rlx2(p);
    while (!((hi_u(v0.x) == tgt) & (hi_u(v0.y) == tgt))) {
        v0 = v1;
        v1 = ld_rlx2(p);
    }
    return v0;
}

// ---------------- clear + seed ----------------
__global__ void clear_kernel(const float* __restrict__ h0) {
    size_t i = (size_t)blockIdx.x * blockDim.x + threadIdx.x;
    if (i < HH) {
        g_p1[i] = packhf(0u, h0[i]);
        g_p2[i] = packhf(0u, h0[HH + i]);
    }
    const size_t N2 = (size_t)TT * HH / 2;
    ulonglong2* a = (ulonglong2*)(g_p1 + HH);
    ulonglong2* b = (ulonglong2*)(g_p2 + HH);
    ulonglong2 z; z.x = 0ull; z.y = 0ull;
    size_t stride = (size_t)gridDim.x * blockDim.x;
    for (size_t k = i; k < N2; k += stride) { a[k] = z; b[k] = z; }
}

// ---------------- persistent pipelined LSTM ----------------
// 129 blocks x 256 threads — exact R10 structure. Changes vs R10:
//   * B-poll (recurrence-critical) is 2-deep pipelined (finer detect sampling)
//   * role-1 resolves A first (has ~1 step slack; usually first-try), then B
//   * head backs off with nanosleep between failed poll rounds (off-critical)
__global__ void __launch_bounds__(256, 1) lstm_kernel(
    const float* __restrict__ x,
    const float* __restrict__ truth,
    const float* __restrict__ c0,
    const float* __restrict__ Wih0, const float* __restrict__ Whh0,
    const float* __restrict__ bih0, const float* __restrict__ bhh0,
    const float* __restrict__ Wih1, const float* __restrict__ Whh1,
    const float* __restrict__ bih1, const float* __restrict__ bhh1,
    const float* __restrict__ Whead, const float* __restrict__ bhead,
    float* __restrict__ out)
{
    const int b  = blockIdx.x;
    const int tt = threadIdx.x;

    // ================= HEAD + LOSS =================
    if (b == 128) {
        if (tt >= 32) return;
        float w0[16], w1[16];
#pragma unroll
        for (int i = 0; i < 16; i++) {
            w0[i] = Whead[tt * 16 + i];
            w1[i] = Whead[HH + tt * 16 + i];
        }
        const float bb0 = bhead[0], bb1 = bhead[1];
        double acc = 0.0;
        const ull* pe = g_p2 + HH + tt * 16;
        for (int t = 0; t < TT; t++, pe += HH) {
            const unsigned tgt = (unsigned)(t + 1);
            ulonglong2 v[8];
            uint pend = 0xFFu;
            bool first = true;
            while (pend) {
                if (!first) __nanosleep(150);   // head lags a full step: free backoff
                first = false;
                ulonglong2 nv[8];
#pragma unroll
                for (int i = 0; i < 8; i++)
                    if (pend & (1u << i)) nv[i] = ld_rlx2(pe + 2 * i);
#pragma unroll
                for (int i = 0; i < 8; i++)
                    if (pend & (1u << i)) {
                        if ((hi_u(nv[i].x) == tgt) & (hi_u(nv[i].y) == tgt)) {
                            v[i] = nv[i];
                            pend &= ~(1u << i);
                        }
                    }
            }
            float s0 = 0.f, s1 = 0.f;
#pragma unroll
            for (int i = 0; i < 8; i++) {
                float h0v = lo_f(v[i].x), h1v = lo_f(v[i].y);
                s0 = fmaf(w0[2 * i], h0v, s0);
                s1 = fmaf(w1[2 * i], h0v, s1);
                s0 = fmaf(w0[2 * i + 1], h1v, s0);
                s1 = fmaf(w1[2 * i + 1], h1v, s1);
            }
#pragma unroll
            for (int m = 16; m >= 1; m >>= 1) {
                s0 += __shfl_xor_sync(0xffffffffu, s0, m);
                s1 += __shfl_xor_sync(0xffffffffu, s1, m);
            }
            if (tt == 0) {
                float z0 = s0 + bb0, z1 = s1 + bb1;
                float y0 = __ldg(truth + t * 2 + 0), y1 = __ldg(truth + t * 2 + 1);
                float t0 = y0 * fmaxf(logsigf_(z0), -100.0f)
                         + (1.0f - y0) * fmaxf(logsigf_(-z0), -100.0f);
                float t1 = y1 * fmaxf(logsigf_(z1), -100.0f)
                         + (1.0f - y1) * fmaxf(logsigf_(-z1), -100.0f);
                acc += (double)t0 + (double)t1;
            }
        }
        if (tt == 0) out[0] = (float)(-acc / (double)(TT * 2));
        return;
    }

    // ================= LSTM layer blocks =================
    const int role = b >> 6;
    const int j0   = (b & 63) * 8;
    const int p    = tt >> 3;           // row pair 0..31
    const int s    = tt & 7;            // 64-col slice
    const bool isB = (p >= 16);
    const int rr0  = 2 * (p & 15);
    const int gate = rr0 >> 3;
    const int jj   = rr0 & 7;

    const float* WM = isB ? (role ? Whh1 : Whh0) : (role ? Wih1 : Wih0);
    const size_t ro = (size_t)(gate * HH + j0 + jj) * HH;

    ulonglong2 w0[16], w1[16];
#pragma unroll
    for (int i = 0; i < 16; i++) {
        int col = s * 64 + 4 * ((i + s) & 15);
        w0[i] = *(const ulonglong2*)(WM + ro + col);
        w1[i] = *(const ulonglong2*)(WM + ro + HH + col);
    }

    // bias folded into A-half s==0 accumulator init
    float biasLo0 = 0.f, biasLo1 = 0.f;
    if (!isB && s == 0) {
        const float* bi = role ? bih1 : bih0;
        const float* bh = role ? bhh1 : bhh0;
        biasLo0 = bi[gate * HH + j0 + jj]     + bh[gate * HH + j0 + jj];
        biasLo1 = bi[gate * HH + j0 + jj + 1] + bh[gate * HH + j0 + jj + 1];
    }

    float c = 0.f;
    if (tt < 8) c = c0[role * HH + j0 + tt];

    __shared__ float vecs[2 * HH];   // [A(512) | B(512)]
    __shared__ float gsum[64];       // transposed: [jj][half*4 + gate]

    ull* myP = role ? g_p2 : g_p1;
    const ull* pA = g_p1 + HH + 2 * tt;        // layer-2 A source: h1 slot t+1
    const ull* pB = myP + 2 * tt;              // own B source: h slot t
    const float2* px = (const float2*)x + tt;  // layer-1 A source
    ull* myOut = myP + HH + j0 + tt;           // producer store (tt<8)

    for (int t = 0; t < TT; t++, pA += HH, pB += HH, px += HH / 2, myOut += HH) {
        const unsigned tgtA = (unsigned)(t + 1);
        const unsigned tgtB = (unsigned)t;
        float2 va, vbv;

        // ---- poll + stage: resolve A (slack stream), then 2-deep B spin ----
        if (role == 0) {
            va = __ldg(px);
        } else {
            ulonglong2 ra;
            for (;;) {
                ra = ld_rlx2(pA);
                if ((hi_u(ra.x) == tgtA) & (hi_u(ra.y) == tgtA)) break;
            }
            va = make_float2(lo_f(ra.x), lo_f(ra.y));
        }
        {
            ulonglong2 rb = pollv2_pipe(pB, tgtB);
            vbv = make_float2(lo_f(rb.x), lo_f(rb.y));
        }
        ((float2*)vecs)[tt] = va;
        ((float2*)(vecs + HH))[tt] = vbv;
        __syncthreads();

        // ---- dual-row packed matvec over this thread's 64-col slice ----
        const float* vb = vecs + (isB ? HH : 0) + s * 64;
        ull a0 = packf2(biasLo0, 0.f);
        ull a1 = packf2(biasLo1, 0.f);
#pragma unroll
        for (int i = 0; i < 16; i++) {
            int idx = 4 * ((i + s) & 15);
            ulonglong2 v = *(const ulonglong2*)(vb + idx);
            ffma2(a0, w0[i].x, v.x);
            ffma2(a0, w0[i].y, v.y);
            ffma2(a1, w1[i].x, v.x);
            ffma2(a1, w1[i].y, v.y);
        }
        float2 f0 = unpack2(a0), f1 = unpack2(a1);
        float s0 = f0.x + f0.y, s1 = f1.x + f1.y;
        s0 += __shfl_xor_sync(0xffffffffu, s0, 1);
        s1 += __shfl_xor_sync(0xffffffffu, s1, 1);
        s0 += __shfl_xor_sync(0xffffffffu, s0, 2);
        s1 += __shfl_xor_sync(0xffffffffu, s1, 2);
        s0 += __shfl_xor_sync(0xffffffffu, s0, 4);
        s1 += __shfl_xor_sync(0xffffffffu, s1, 4);
        if (s == 0) {
            int half4 = isB ? 4 : 0;
            gsum[jj * 8 + half4 + gate]       = s0;   // row rr0
            gsum[(jj + 1) * 8 + half4 + gate] = s1;   // row rr0+1
        }
        __syncthreads();

        // ---- gates + cell update + publish ----
        if (tt < 8) {
            float4 qa = *(const float4*)(gsum + tt * 8);       // A: i,f,g,o (biased)
            float4 qb = *(const float4*)(gsum + tt * 8 + 4);   // B: i,f,g,o
            float ig = sig_fast(qa.x + qb.x);
            float fg = sig_fast(qa.y + qb.y);
            float gg = tanh_fast(qa.z + qb.z);
            float og = sig_fast(qa.w + qb.w);
            c = fg * c + ig * gg;
            float h = og * tanh_fast(c);
            st_rlx(myOut, packhf((unsigned)(t + 1), h));
        }
    }
}

extern "C" void kernel_launch(void* const* d_in, const int* in_sizes, int n_in,
                              void* d_out, int out_size) {
    const float* x     = (const float*)d_in[0];
    const float* truth = (const float*)d_in[1];
    const float* h0    = (const float*)d_in[2];
    const float* c0    = (const float*)d_in[3];
    const float* Wih0  = (const float*)d_in[4];
    const float* Whh0  = (const float*)d_in[5];
    const float* bih0  = (const float*)d_in[6];
    const float* bhh0  = (const float*)d_in[7];
    const float* Wih1  = (const float*)d_in[8];
    const float* Whh1  = (const float*)d_in[9];
    const float* bih1  = (const float*)d_in[10];
    const float* bhh1  = (const float*)d_in[11];
    const float* Whead = (const float*)d_in[12];
    const float* bhead = (const float*)d_in[13];
    float* out = (float*)d_out;

    clear_kernel<<<256, 1024>>>(h0);
    lstm_kernel<<<129, 256>>>(x, truth, c0,
                              Wih0, Whh0, bih0, bhh0,
                              Wih1, Whh1, bih1, bhh1,
                              Whead, bhead, out);
}

// round 14
// speedup vs baseline: 1.4407x; 1.4407x over previous
#include <cuda_runtime.h>
#include <math.h>

typedef unsigned long long ull;
typedef unsigned int uint;

#define TT 8192
#define HH 512

// ---------------- scratch: packed {flag(hi32), h_bits(lo32)} mailboxes ----------------
__device__ __align__(256) ull g_p1[(TT + 1) * HH];
__device__ __align__(256) ull g_p2[(TT + 1) * HH];

// ---------------- primitives ----------------
__device__ __forceinline__ ulonglong2 ld_rlx2(const ull* p) {
    ulonglong2 v;
    asm volatile("ld.relaxed.gpu.global.v2.u64 {%0,%1}, [%2];"
                 : "=l"(v.x), "=l"(v.y) : "l"(p) : "memory");
    return v;
}
__device__ __forceinline__ void st_rlx(ull* p, ull v) {
    asm volatile("st.relaxed.gpu.global.u64 [%0], %1;" :: "l"(p), "l"(v) : "memory");
}
__device__ __forceinline__ ull packhf(unsigned flag, float h) {
    return ((ull)flag << 32) | (ull)__float_as_uint(h);
}
__device__ __forceinline__ float lo_f(ull v) { return __uint_as_float((unsigned)v); }
__device__ __forceinline__ unsigned hi_u(ull v) { return (unsigned)(v >> 32); }

__device__ __forceinline__ void ffma2(ull& acc, ull w, ull v) {
    asm("fma.rn.f32x2 %0, %1, %2, %0;" : "+l"(acc) : "l"(w), "l"(v));
}
__device__ __forceinline__ ull packf2(float a, float b) {
    ull r;
    asm("mov.b64 %0, {%1,%2};" : "=l"(r) : "f"(a), "f"(b));
    return r;
}
__device__ __forceinline__ float2 unpack2(ull v) {
    float a, b;
    asm("mov.b64 {%0,%1}, %2;" : "=f"(a), "=f"(b) : "l"(v));
    return make_float2(a, b);
}
__device__ __forceinline__ float tanh_fast(float x) {
    float r;
    asm("tanh.approx.f32 %0, %1;" : "=f"(r) : "f"(x));
    return r;
}
__device__ __forceinline__ float sig_fast(float x) {
    return fmaf(tanh_fast(0.5f * x), 0.5f, 0.5f);
}
__device__ __forceinline__ float logsigf_(float z) {
    if (z >= 0.0f) return -log1pf(expf(-z));
    return z - log1pf(expf(z));
}

// ---------------- clear + seed ----------------
__global__ void clear_kernel(const float* __restrict__ h0) {
    size_t i = (size_t)blockIdx.x * blockDim.x + threadIdx.x;
    if (i < HH) {
        g_p1[i] = packhf(0u, h0[i]);
        g_p2[i] = packhf(0u, h0[HH + i]);
    }
    const size_t N2 = (size_t)TT * HH / 2;
    ulonglong2* a = (ulonglong2*)(g_p1 + HH);
    ulonglong2* b = (ulonglong2*)(g_p2 + HH);
    ulonglong2 z; z.x = 0ull; z.y = 0ull;
    size_t stride = (size_t)gridDim.x * blockDim.x;
    for (size_t k = i; k < N2; k += stride) { a[k] = z; b[k] = z; }
}

// ---------------- persistent pipelined LSTM ----------------
// 129 blocks x 256 threads — exact R10 structure (10.35ms). Changes vs R10:
//   * head backs off with nanosleep between failed poll rounds (off-critical
//     traffic removal on the very lines layer-2 stores/polls)
//   * producers (gate threads) live in warp 7 — hi-wid-first arbiter selects
//     the gate warp FIRST after bar2 release instead of last
__global__ void __launch_bounds__(256, 1) lstm_kernel(
    const float* __restrict__ x,
    const float* __restrict__ truth,
    const float* __restrict__ c0,
    const float* __restrict__ Wih0, const float* __restrict__ Whh0,
    const float* __restrict__ bih0, const float* __restrict__ bhh0,
    const float* __restrict__ Wih1, const float* __restrict__ Whh1,
    const float* __restrict__ bih1, const float* __restrict__ bhh1,
    const float* __restrict__ Whead, const float* __restrict__ bhead,
    float* __restrict__ out)
{
    const int b  = blockIdx.x;
    const int tt = threadIdx.x;

    // ================= HEAD + LOSS =================
    if (b == 128) {
        if (tt >= 32) return;
        float w0[16], w1[16];
#pragma unroll
        for (int i = 0; i < 16; i++) {
            w0[i] = Whead[tt * 16 + i];
            w1[i] = Whead[HH + tt * 16 + i];
        }
        const float bb0 = bhead[0], bb1 = bhead[1];
        double acc = 0.0;
        const ull* pe = g_p2 + HH + tt * 16;
        for (int t = 0; t < TT; t++, pe += HH) {
            const unsigned tgt = (unsigned)(t + 1);
            ulonglong2 v[8];
            uint pend = 0xFFu;
            bool first = true;
            while (pend) {
                if (!first) __nanosleep(150);   // head lags a full step: free backoff
                first = false;
                ulonglong2 nv[8];
#pragma unroll
                for (int i = 0; i < 8; i++)
                    if (pend & (1u << i)) nv[i] = ld_rlx2(pe + 2 * i);
#pragma unroll
                for (int i = 0; i < 8; i++)
                    if (pend & (1u << i)) {
                        if ((hi_u(nv[i].x) == tgt) & (hi_u(nv[i].y) == tgt)) {
                            v[i] = nv[i];
                            pend &= ~(1u << i);
                        }
                    }
            }
            float s0 = 0.f, s1 = 0.f;
#pragma unroll
            for (int i = 0; i < 8; i++) {
                float h0v = lo_f(v[i].x), h1v = lo_f(v[i].y);
                s0 = fmaf(w0[2 * i], h0v, s0);
                s1 = fmaf(w1[2 * i], h0v, s1);
                s0 = fmaf(w0[2 * i + 1], h1v, s0);
                s1 = fmaf(w1[2 * i + 1], h1v, s1);
            }
#pragma unroll
            for (int m = 16; m >= 1; m >>= 1) {
                s0 += __shfl_xor_sync(0xffffffffu, s0, m);
                s1 += __shfl_xor_sync(0xffffffffu, s1, m);
            }
            if (tt == 0) {
                float z0 = s0 + bb0, z1 = s1 + bb1;
                float y0 = __ldg(truth + t * 2 + 0), y1 = __ldg(truth + t * 2 + 1);
                float t0 = y0 * fmaxf(logsigf_(z0), -100.0f)
                         + (1.0f - y0) * fmaxf(logsigf_(-z0), -100.0f);
                float t1 = y1 * fmaxf(logsigf_(z1), -100.0f)
                         + (1.0f - y1) * fmaxf(logsigf_(-z1), -100.0f);
                acc += (double)t0 + (double)t1;
            }
        }
        if (tt == 0) out[0] = (float)(-acc / (double)(TT * 2));
        return;
    }

    // ================= LSTM layer blocks =================
    const int role = b >> 6;
    const int j0   = (b & 63) * 8;
    const int p    = tt >> 3;           // row pair 0..31
    const int s    = tt & 7;            // 64-col slice
    const bool isB = (p >= 16);
    const int rr0  = 2 * (p & 15);
    const int gate = rr0 >> 3;
    const int jj   = rr0 & 7;

    const float* WM = isB ? (role ? Whh1 : Whh0) : (role ? Wih1 : Wih0);
    const size_t ro = (size_t)(gate * HH + j0 + jj) * HH;

    ulonglong2 w0[16], w1[16];
#pragma unroll
    for (int i = 0; i < 16; i++) {
        int col = s * 64 + 4 * ((i + s) & 15);
        w0[i] = *(const ulonglong2*)(WM + ro + col);
        w1[i] = *(const ulonglong2*)(WM + ro + HH + col);
    }

    // bias folded into A-half s==0 accumulator init
    float biasLo0 = 0.f, biasLo1 = 0.f;
    if (!isB && s == 0) {
        const float* bi = role ? bih1 : bih0;
        const float* bh = role ? bhh1 : bhh0;
        biasLo0 = bi[gate * HH + j0 + jj]     + bh[gate * HH + j0 + jj];
        biasLo1 = bi[gate * HH + j0 + jj + 1] + bh[gate * HH + j0 + jj + 1];
    }

    // producers in warp 7 (tt 248..255): first-selected after bar2 release
    const bool isProd = (tt >= 248);
    const int  jp     = tt & 7;         // producer's output index 0..7 (for tt>=248)
    float c = 0.f;
    if (isProd) c = c0[role * HH + j0 + jp];

    __shared__ float vecs[2 * HH];   // [A(512) | B(512)]
    __shared__ float gsum[64];       // transposed: [jj][half*4 + gate]

    ull* myP = role ? g_p2 : g_p1;
    const ull* pA = g_p1 + HH + 2 * tt;        // layer-2 A source: h1 slot t+1
    const ull* pB = myP + 2 * tt;              // own B source: h slot t
    const float2* px = (const float2*)x + tt;  // layer-1 A source
    ull* myOut = myP + HH + j0 + jp;           // producer store (warp 7)

    for (int t = 0; t < TT; t++, pA += HH, pB += HH, px += HH / 2, myOut += HH) {
        const unsigned tgtA = (unsigned)(t + 1);
        const unsigned tgtB = (unsigned)t;
        float2 va, vbv;

        // ---- concurrent A+B v2 poll (R10-proven shape) ----
        if (role == 0) {
            va = __ldg(px);
            ulonglong2 rb;
            for (;;) {
                rb = ld_rlx2(pB);
                if ((hi_u(rb.x) == tgtB) & (hi_u(rb.y) == tgtB)) break;
            }
            vbv = make_float2(lo_f(rb.x), lo_f(rb.y));
        } else {
            ulonglong2 ra, rb;
            bool okA = false, okB = false;
            do {
                ulonglong2 na, nb;
                if (!okA) na = ld_rlx2(pA);
                if (!okB) nb = ld_rlx2(pB);
                if (!okA) {
                    if ((hi_u(na.x) == tgtA) & (hi_u(na.y) == tgtA)) { ra = na; okA = true; }
                }
                if (!okB) {
                    if ((hi_u(nb.x) == tgtB) & (hi_u(nb.y) == tgtB)) { rb = nb; okB = true; }
                }
            } while (!(okA & okB));
            va  = make_float2(lo_f(ra.x), lo_f(ra.y));
            vbv = make_float2(lo_f(rb.x), lo_f(rb.y));
        }
        ((float2*)vecs)[tt] = va;
        ((float2*)(vecs + HH))[tt] = vbv;
        __syncthreads();

        // ---- dual-row packed matvec over this thread's 64-col slice ----
        const float* vb = vecs + (isB ? HH : 0) + s * 64;
        ull a0 = packf2(biasLo0, 0.f);
        ull a1 = packf2(biasLo1, 0.f);
#pragma unroll
        for (int i = 0; i < 16; i++) {
            int idx = 4 * ((i + s) & 15);
            ulonglong2 v = *(const ulonglong2*)(vb + idx);
            ffma2(a0, w0[i].x, v.x);
            ffma2(a0, w0[i].y, v.y);
            ffma2(a1, w1[i].x, v.x);
            ffma2(a1, w1[i].y, v.y);
        }
        float2 f0 = unpack2(a0), f1 = unpack2(a1);
        float s0 = f0.x + f0.y, s1 = f1.x + f1.y;
        s0 += __shfl_xor_sync(0xffffffffu, s0, 1);
        s1 += __shfl_xor_sync(0xffffffffu, s1, 1);
        s0 += __shfl_xor_sync(0xffffffffu, s0, 2);
        s1 += __shfl_xor_sync(0xffffffffu, s1, 2);
        s0 += __shfl_xor_sync(0xffffffffu, s0, 4);
        s1 += __shfl_xor_sync(0xffffffffu, s1, 4);
        if (s == 0) {
            int half4 = isB ? 4 : 0;
            gsum[jj * 8 + half4 + gate]       = s0;   // row rr0
            gsum[(jj + 1) * 8 + half4 + gate] = s1;   // row rr0+1
        }
        __syncthreads();

        // ---- gates + cell update + publish (warp 7) ----
        if (isProd) {
            float4 qa = *(const float4*)(gsum + jp * 8);       // A: i,f,g,o (biased)
            float4 qb = *(const float4*)(gsum + jp * 8 + 4);   // B: i,f,g,o
            float ig = sig_fast(qa.x + qb.x);
            float fg = sig_fast(qa.y + qb.y);
            float gg = tanh_fast(qa.z + qb.z);
            float og = sig_fast(qa.w + qb.w);
            c = fg * c + ig * gg;
            float h = og * tanh_fast(c);
            st_rlx(myOut, packhf((unsigned)(t + 1), h));
        }
    }
}

extern "C" void kernel_launch(void* const* d_in, const int* in_sizes, int n_in,
                              void* d_out, int out_size) {
    const float* x     = (const float*)d_in[0];
    const float* truth = (const float*)d_in[1];
    const float* h0    = (const float*)d_in[2];
    const float* c0    = (const float*)d_in[3];
    const float* Wih0  = (const float*)d_in[4];
    const float* Whh0  = (const float*)d_in[5];
    const float* bih0  = (const float*)d_in[6];
    const float* bhh0  = (const float*)d_in[7];
    const float* Wih1  = (const float*)d_in[8];
    const float* Whh1  = (const float*)d_in[9];
    const float* bih1  = (const float*)d_in[10];
    const float* bhh1  = (const float*)d_in[11];
    const float* Whead = (const float*)d_in[12];
    const float* bhead = (const float*)d_in[13];
    float* out = (float*)d_out;

    clear_kernel<<<256, 1024>>>(h0);
    lstm_kernel<<<129, 256>>>(x, truth, c0,
                              Wih0, Whh0, bih0, bhh0,
                              Wih1, Whh1, bih1, bhh1,
                              Whead, bhead, out);
}